// round 1
// baseline (speedup 1.0000x reference)
#include <cuda_runtime.h>
#include <math.h>

#define N_    4096
#define B_    16
#define NT_   500
#define GRID_ 128
#define TPB_  256
#define NSLICE 16
#define KSL   256   // k per slice (NSLICE*KSL == N_)

// ---------------- persistent device state (allowed: __device__ globals) ----
__device__ float g_Wt[(size_t)N_ * N_];          // Wt[k*N_ + n] = W[n*N_ + k]   (64 MB)
__device__ float g_Yp[N_ * B_];                  // Yp[k*B_ + b]                 (256 KB)
__device__ float g_Zpart[NSLICE * N_ * B_];      // [slice][n][b]                (4 MB)
__device__ unsigned g_count = 0;
__device__ unsigned g_sense = 0;

typedef unsigned long long u64;

// ---------------- packed f32x2 helpers (Blackwell FFMA2: PTX-only) --------
__device__ __forceinline__ u64 pack2(float x) {
    u64 r; asm("mov.b64 %0, {%1, %1};" : "=l"(r) : "f"(x)); return r;
}
__device__ __forceinline__ void fma2(u64& d, u64 a, u64 b) {
    asm("fma.rn.f32x2 %0, %1, %2, %0;" : "+l"(d) : "l"(a), "l"(b));
}
// L2-only loads (data is mutated by other SMs inside the persistent kernel;
// L1 is NOT coherent, so .cg is load-bearing for correctness)
__device__ __forceinline__ void ldy2(u64& a, u64& b, const float* p) {
    asm("ld.global.cg.v2.u64 {%0, %1}, [%2];" : "=l"(a), "=l"(b) : "l"(p));
}
__device__ __forceinline__ float ldcg(const float* p) {
    float v; asm("ld.global.cg.f32 %0, [%1];" : "=f"(v) : "l"(p)); return v;
}

// ---------------- grid-wide sense-reversing barrier -----------------------
// Total barriers per launch is EVEN, so g_sense/g_count return to (0,0)
// before the next graph replay (device globals persist across replays).
__device__ __forceinline__ void grid_barrier(unsigned& lsense) {
    __syncthreads();
    if (threadIdx.x == 0) {
        unsigned s = lsense ^ 1u;
        __threadfence();
        if (atomicAdd(&g_count, 1u) == GRID_ - 1u) {
            atomicExch(&g_count, 0u);
            __threadfence();
            atomicExch(&g_sense, s);
        } else {
            volatile unsigned* gs = &g_sense;
            while (*gs != s) { }
            __threadfence();
        }
        lsense = s;
    }
    __syncthreads();
}

// ---------------- main persistent kernel ----------------------------------
__global__ void __launch_bounds__(TPB_, 1)
snn_kernel(const float* __restrict__ W, const float* __restrict__ x0,
           const float* __restrict__ V0, const float* __restrict__ Y0,
           float* __restrict__ out)
{
    const int g = blockIdx.x;
    const int t = threadIdx.x;
    unsigned lsense = 0;

    // ---- init A: tiled transpose W -> g_Wt (coalesced both sides) ----
    {
        __shared__ float tile[32][33];
        const int TPR = N_ / 32;            // 128 tiles per side
        const int i = t >> 5, j = t & 31;   // 8 rows x 32 cols per pass
        for (int tt = g; tt < TPR * TPR; tt += GRID_) {
            const int trow = tt / TPR;      // n-block
            const int tcol = tt % TPR;      // k-block
            #pragma unroll
            for (int r = 0; r < 32; r += 8)
                tile[r + i][j] = W[(size_t)(trow * 32 + r + i) * N_ + tcol * 32 + j];
            __syncthreads();
            #pragma unroll
            for (int r = 0; r < 32; r += 8)
                g_Wt[(size_t)(tcol * 32 + r + i) * N_ + trow * 32 + j] = tile[j][r + i];
            __syncthreads();
        }
    }

    // ---- init B: pack Y0 -> Yp[k][b] ----
    for (int m = g * TPB_ + t; m < N_ * B_; m += GRID_ * TPB_) {
        const int k = m >> 4, b = m & 15;
        g_Yp[m] = Y0[b * N_ + k];
    }

    // ---- per-thread neuron state, kept in registers for all 500 steps ----
    const int u  = g * TPB_ + t;            // 0..32767
    const int m0 = u, m1 = u + GRID_ * TPB_;
    const int k0n = m0 >> 4, b0n = m0 & 15;
    const int k1n = m1 >> 4, b1n = m1 & 15;
    float Vr0 = V0[b0n * N_ + k0n], Vr1 = V0[b1n * N_ + k1n];
    float Yr0 = Y0[b0n * N_ + k0n], Yr1 = Y0[b1n * N_ + k1n];
    const float xr0 = x0[b0n * N_ + k0n], xr1 = x0[b1n * N_ + k1n];
    float Rr0 = 0.0f, Rr1 = 0.0f;

    // ---- GEMM task mapping: (n-tile, k-slice) ----
    const int nt = g >> 3;                       // 0..15  (256 n each)
    const int n  = nt * 256 + 2 * (t & 127);     // this thread's n pair
    const int sl = 2 * (g & 7) + (t >> 7);       // k-slice 0..15
    const float* wt_base = g_Wt + (size_t)sl * KSL * N_ + n;
    float*       zp      = g_Zpart + ((size_t)sl * N_ + n) * B_;
    const float* yb      = g_Yp + sl * KSL * B_;

    grid_barrier(lsense);                        // barrier 1: init done

    const float cY    = (float)(0.1 / 8.0);      // dt / tausyn
    const float scale = (float)(0.1 / (500 * 0.1)); // dt / T

    for (int step = 0; step < NT_; ++step) {
        // ======== phase 1: partial GEMM (2 n-rows x 16 batches, 256 k) ====
        u64 A0[8], A1[8];
        #pragma unroll
        for (int j = 0; j < 8; ++j) { A0[j] = 0ull; A1[j] = 0ull; }

        const float* wp = wt_base;
        const float* yp = yb;
        #pragma unroll 4
        for (int kk = 0; kk < KSL; ++kk) {
            const float2 w2 = *reinterpret_cast<const float2*>(wp);
            const u64 w0 = pack2(w2.x);
            const u64 w1 = pack2(w2.y);
            u64 y0, y1, y2, y3, y4, y5, y6, y7;
            ldy2(y0, y1, yp);
            ldy2(y2, y3, yp + 4);
            ldy2(y4, y5, yp + 8);
            ldy2(y6, y7, yp + 12);
            fma2(A0[0], w0, y0); fma2(A1[0], w1, y0);
            fma2(A0[1], w0, y1); fma2(A1[1], w1, y1);
            fma2(A0[2], w0, y2); fma2(A1[2], w1, y2);
            fma2(A0[3], w0, y3); fma2(A1[3], w1, y3);
            fma2(A0[4], w0, y4); fma2(A1[4], w1, y4);
            fma2(A0[5], w0, y5); fma2(A1[5], w1, y5);
            fma2(A0[6], w0, y6); fma2(A1[6], w1, y6);
            fma2(A0[7], w0, y7); fma2(A1[7], w1, y7);
            wp += N_;
            yp += B_;
        }
        // store 32 partials (two contiguous 64B rows)
        {
            union F2 { u64 u; float2 f; };
            float4* z4 = reinterpret_cast<float4*>(zp);
            #pragma unroll
            for (int j = 0; j < 4; ++j) {
                F2 a{A0[2 * j]}, b{A0[2 * j + 1]};
                z4[j] = make_float4(a.f.x, a.f.y, b.f.x, b.f.y);
            }
            #pragma unroll
            for (int j = 0; j < 4; ++j) {
                F2 a{A1[2 * j]}, b{A1[2 * j + 1]};
                z4[4 + j] = make_float4(a.f.x, a.f.y, b.f.x, b.f.y);
            }
        }

        grid_barrier(lsense);                    // partials visible

        // ======== phase 2: neuron update (2 items, state in registers) ====
        {
            float Z = xr0;
            #pragma unroll
            for (int s2 = 0; s2 < NSLICE; ++s2)
                Z += ldcg(g_Zpart + ((size_t)s2 * N_ + k0n) * B_ + b0n);
            float num = -(Vr0 - (-72.0f));
            num = num + expf(Vr0 - (-55.0f));
            num = num + Z;
            const float dV = num / 10.0f;
            float Vn = Vr0 + 0.1f * dV;
            Vn = fmaxf(Vn, -85.0f);
            const bool sp = (Vn >= 0.0f);
            const float S = sp ? 10.0f : 0.0f;
            if (sp) Vn = -72.0f;
            Vr0 = Vn;
            Yr0 = Yr0 + cY * (S - Yr0);
            Rr0 += S;
            g_Yp[m0] = Yr0;
        }
        {
            float Z = xr1;
            #pragma unroll
            for (int s2 = 0; s2 < NSLICE; ++s2)
                Z += ldcg(g_Zpart + ((size_t)s2 * N_ + k1n) * B_ + b1n);
            float num = -(Vr1 - (-72.0f));
            num = num + expf(Vr1 - (-55.0f));
            num = num + Z;
            const float dV = num / 10.0f;
            float Vn = Vr1 + 0.1f * dV;
            Vn = fmaxf(Vn, -85.0f);
            const bool sp = (Vn >= 0.0f);
            const float S = sp ? 10.0f : 0.0f;
            if (sp) Vn = -72.0f;
            Vr1 = Vn;
            Yr1 = Yr1 + cY * (S - Yr1);
            Rr1 += S;
            g_Yp[m1] = Yr1;
        }

        grid_barrier(lsense);                    // Yp visible for next step
    }

    // ---- output: r * dt/T  (layout out[b][n]) ----
    out[b0n * N_ + k0n] = Rr0 * scale;
    out[b1n * N_ + k1n] = Rr1 * scale;

    grid_barrier(lsense);  // pad: total = 1 + 2*NT_ + 1 = 1002 (even)
}

extern "C" void kernel_launch(void* const* d_in, const int* in_sizes, int n_in,
                              void* d_out, int out_size)
{
    (void)in_sizes; (void)n_in; (void)out_size;
    const float* W  = (const float*)d_in[0];
    const float* x0 = (const float*)d_in[1];
    const float* V0 = (const float*)d_in[2];
    const float* Y0 = (const float*)d_in[3];
    snn_kernel<<<GRID_, TPB_>>>(W, x0, V0, Y0, (float*)d_out);
}

// round 2
// speedup vs baseline: 1.6822x; 1.6822x over previous
#include <cuda_runtime.h>
#include <math.h>

#define N_    4096
#define B_    16
#define NT_   500
#define GRID_ 128
#define TPB_  256
#define NSLICE 16
#define KSL   256   // k per slice (NSLICE*KSL == N_)

// ---------------- persistent device state (allowed: __device__ globals) ----
__device__ float g_Wt[(size_t)N_ * N_];          // Wt[k*N_ + n] = W[n*N_ + k]   (64 MB)
__device__ float g_Yp[N_ * B_];                  // Yp[k*B_ + b]                 (256 KB)
__device__ float g_Zpart[NSLICE * N_ * B_];      // [slice][n][b]                (4 MB)
__device__ unsigned g_count = 0;
__device__ unsigned g_sense = 0;

typedef unsigned long long u64;

// ---------------- packed f32x2 helpers (Blackwell FFMA2: PTX-only) --------
__device__ __forceinline__ u64 pack2(float x) {
    u64 r; asm("mov.b64 %0, {%1, %1};" : "=l"(r) : "f"(x)); return r;
}
__device__ __forceinline__ void fma2(u64& d, u64 a, u64 b) {
    asm("fma.rn.f32x2 %0, %1, %2, %0;" : "+l"(d) : "l"(a), "l"(b));
}
// L2-only loads for cross-SM-mutated data (L1 not coherent within a
// persistent kernel -> .cg is load-bearing for correctness)
__device__ __forceinline__ float4 ldcg4(const float* p) {
    float4 v;
    asm("ld.global.cg.v4.f32 {%0,%1,%2,%3}, [%4];"
        : "=f"(v.x), "=f"(v.y), "=f"(v.z), "=f"(v.w) : "l"(p));
    return v;
}
__device__ __forceinline__ float ldcg(const float* p) {
    float v; asm("ld.global.cg.f32 %0, [%1];" : "=f"(v) : "l"(p)); return v;
}

// ---------------- grid-wide sense-reversing barrier -----------------------
// Total barriers per launch is EVEN, so g_sense/g_count return to (0,0)
// before the next graph replay (device globals persist across replays).
__device__ __forceinline__ void grid_barrier(unsigned& lsense) {
    __syncthreads();
    if (threadIdx.x == 0) {
        unsigned s = lsense ^ 1u;
        __threadfence();
        if (atomicAdd(&g_count, 1u) == GRID_ - 1u) {
            atomicExch(&g_count, 0u);
            __threadfence();
            atomicExch(&g_sense, s);
        } else {
            volatile unsigned* gs = &g_sense;
            while (*gs != s) { }
            __threadfence();
        }
        lsense = s;
    }
    __syncthreads();
}

// ---------------- main persistent kernel ----------------------------------
__global__ void __launch_bounds__(TPB_, 1)
snn_kernel(const float* __restrict__ W, const float* __restrict__ x0,
           const float* __restrict__ V0, const float* __restrict__ Y0,
           float* __restrict__ out)
{
    // Y staged in smem: 2 slices x 256 k x 16 b  (32 KB)
    __shared__ float Ys[2 * KSL * B_];
    __shared__ float tile[32][33];

    const int g = blockIdx.x;
    const int t = threadIdx.x;
    unsigned lsense = 0;

    // ---- init A: tiled transpose W -> g_Wt (coalesced both sides) ----
    {
        const int TPR = N_ / 32;            // 128 tiles per side
        const int i = t >> 5, j = t & 31;   // 8 rows x 32 cols per pass
        for (int tt = g; tt < TPR * TPR; tt += GRID_) {
            const int trow = tt / TPR;      // n-block
            const int tcol = tt % TPR;      // k-block
            #pragma unroll
            for (int r = 0; r < 32; r += 8)
                tile[r + i][j] = W[(size_t)(trow * 32 + r + i) * N_ + tcol * 32 + j];
            __syncthreads();
            #pragma unroll
            for (int r = 0; r < 32; r += 8)
                g_Wt[(size_t)(tcol * 32 + r + i) * N_ + trow * 32 + j] = tile[j][r + i];
            __syncthreads();
        }
    }

    // ---- init B: pack Y0 -> Yp[k][b] ----
    for (int m = g * TPB_ + t; m < N_ * B_; m += GRID_ * TPB_) {
        const int k = m >> 4, b = m & 15;
        g_Yp[m] = Y0[b * N_ + k];
    }

    // ---- per-thread neuron state, kept in registers for all 500 steps ----
    const int u  = g * TPB_ + t;            // 0..32767
    const int m0 = u, m1 = u + GRID_ * TPB_;
    const int k0n = m0 >> 4, b0n = m0 & 15;
    const int k1n = m1 >> 4, b1n = m1 & 15;
    float Vr0 = V0[b0n * N_ + k0n], Vr1 = V0[b1n * N_ + k1n];
    float Yr0 = Y0[b0n * N_ + k0n], Yr1 = Y0[b1n * N_ + k1n];
    const float xr0 = x0[b0n * N_ + k0n], xr1 = x0[b1n * N_ + k1n];
    float Rr0 = 0.0f, Rr1 = 0.0f;

    // ---- GEMM task mapping: (n-tile, k-slice) ----
    const int nt  = g >> 3;                      // 0..15  (256 n each)
    const int n   = nt * 256 + 2 * (t & 127);    // this thread's n pair
    const int h   = t >> 7;                      // which of the block's 2 slices
    const int sl0 = 2 * (g & 7);                 // first slice of this block
    const int sl  = sl0 + h;                     // k-slice 0..15
    const float* wt_base = g_Wt + (size_t)sl * KSL * N_ + n;
    float*       zp      = g_Zpart + ((size_t)sl * N_ + n) * B_;
    const float* yg      = g_Yp + sl0 * KSL * B_;   // 32 KB contiguous (2 slices)
    const float* ysm     = Ys + h * (KSL * B_);

    grid_barrier(lsense);                        // barrier 1: init done

    const float cY    = (float)(0.1 / 8.0);         // dt / tausyn
    const float scale = (float)(0.1 / (500 * 0.1)); // dt / T

    for (int step = 0; step < NT_; ++step) {
        // ---- stage this block's 2 Y slices into smem (coalesced, L2 reads)
        #pragma unroll
        for (int i = 0; i < (2 * KSL * B_) / (4 * TPB_); ++i) {  // 8 float4 per thread
            const int idx = (i * TPB_ + t) * 4;
            const float4 v = ldcg4(yg + idx);
            *reinterpret_cast<float4*>(&Ys[idx]) = v;
        }
        __syncthreads();

        // ======== phase 1: partial GEMM (2 n-rows x 16 batches, 256 k) ====
        u64 A0[8], A1[8];
        #pragma unroll
        for (int j = 0; j < 8; ++j) { A0[j] = 0ull; A1[j] = 0ull; }

        const float* wp = wt_base;
        #pragma unroll 8
        for (int kk = 0; kk < KSL; ++kk) {
            const float2 w2 = *reinterpret_cast<const float2*>(wp);
            const u64 w0 = pack2(w2.x);
            const u64 w1 = pack2(w2.y);
            // Y row from smem: same address across the warp -> LDS broadcast
            const ulonglong2* yrow =
                reinterpret_cast<const ulonglong2*>(ysm + kk * B_);
            const ulonglong2 p0 = yrow[0];
            const ulonglong2 p1 = yrow[1];
            const ulonglong2 p2 = yrow[2];
            const ulonglong2 p3 = yrow[3];
            fma2(A0[0], w0, p0.x); fma2(A1[0], w1, p0.x);
            fma2(A0[1], w0, p0.y); fma2(A1[1], w1, p0.y);
            fma2(A0[2], w0, p1.x); fma2(A1[2], w1, p1.x);
            fma2(A0[3], w0, p1.y); fma2(A1[3], w1, p1.y);
            fma2(A0[4], w0, p2.x); fma2(A1[4], w1, p2.x);
            fma2(A0[5], w0, p2.y); fma2(A1[5], w1, p2.y);
            fma2(A0[6], w0, p3.x); fma2(A1[6], w1, p3.x);
            fma2(A0[7], w0, p3.y); fma2(A1[7], w1, p3.y);
            wp += N_;
        }
        // store 32 partials (two contiguous 64B rows)
        {
            union F2 { u64 u; float2 f; };
            float4* z4 = reinterpret_cast<float4*>(zp);
            #pragma unroll
            for (int j = 0; j < 4; ++j) {
                F2 a{A0[2 * j]}, b{A0[2 * j + 1]};
                z4[j] = make_float4(a.f.x, a.f.y, b.f.x, b.f.y);
            }
            #pragma unroll
            for (int j = 0; j < 4; ++j) {
                F2 a{A1[2 * j]}, b{A1[2 * j + 1]};
                z4[4 + j] = make_float4(a.f.x, a.f.y, b.f.x, b.f.y);
            }
        }

        grid_barrier(lsense);                    // partials visible

        // ======== phase 2: neuron update (2 items, state in registers) ====
        {
            float Z = xr0;
            #pragma unroll
            for (int s2 = 0; s2 < NSLICE; ++s2)
                Z += ldcg(g_Zpart + ((size_t)s2 * N_ + k0n) * B_ + b0n);
            float num = -(Vr0 - (-72.0f));
            num = num + expf(Vr0 - (-55.0f));
            num = num + Z;
            const float dV = num / 10.0f;
            float Vn = Vr0 + 0.1f * dV;
            Vn = fmaxf(Vn, -85.0f);
            const bool sp = (Vn >= 0.0f);
            const float S = sp ? 10.0f : 0.0f;
            if (sp) Vn = -72.0f;
            Vr0 = Vn;
            Yr0 = Yr0 + cY * (S - Yr0);
            Rr0 += S;
            g_Yp[m0] = Yr0;
        }
        {
            float Z = xr1;
            #pragma unroll
            for (int s2 = 0; s2 < NSLICE; ++s2)
                Z += ldcg(g_Zpart + ((size_t)s2 * N_ + k1n) * B_ + b1n);
            float num = -(Vr1 - (-72.0f));
            num = num + expf(Vr1 - (-55.0f));
            num = num + Z;
            const float dV = num / 10.0f;
            float Vn = Vr1 + 0.1f * dV;
            Vn = fmaxf(Vn, -85.0f);
            const bool sp = (Vn >= 0.0f);
            const float S = sp ? 10.0f : 0.0f;
            if (sp) Vn = -72.0f;
            Vr1 = Vn;
            Yr1 = Yr1 + cY * (S - Yr1);
            Rr1 += S;
            g_Yp[m1] = Yr1;
        }

        grid_barrier(lsense);                    // Yp visible for next step
    }

    // ---- output: r * dt/T  (layout out[b][n]) ----
    out[b0n * N_ + k0n] = Rr0 * scale;
    out[b1n * N_ + k1n] = Rr1 * scale;

    grid_barrier(lsense);  // pad: total = 1 + 2*NT_ + 1 = 1002 (even)
}

extern "C" void kernel_launch(void* const* d_in, const int* in_sizes, int n_in,
                              void* d_out, int out_size)
{
    (void)in_sizes; (void)n_in; (void)out_size;
    const float* W  = (const float*)d_in[0];
    const float* x0 = (const float*)d_in[1];
    const float* V0 = (const float*)d_in[2];
    const float* Y0 = (const float*)d_in[3];
    snn_kernel<<<GRID_, TPB_>>>(W, x0, V0, Y0, (float*)d_out);
}

// round 3
// speedup vs baseline: 1.7838x; 1.0604x over previous
#include <cuda_runtime.h>
#include <math.h>

#define N_    4096
#define B_    16
#define NT_   500
#define GRID_ 128
#define TPB_  256
#define NSLICE 32
#define KSL   128   // k per slice (NSLICE*KSL == N_)

// ---------------- persistent device state (allowed: __device__ globals) ----
__device__ float g_Wt[(size_t)N_ * N_];          // Wt[k*N_ + n] = W[n*N_ + k]   (64 MB)
__device__ float g_Yp[N_ * B_];                  // Yp[k*B_ + b]                 (256 KB)
__device__ float g_Zpart[NSLICE * N_ * B_];      // [slice][n][b]                (8 MB)
__device__ unsigned g_count = 0;
__device__ unsigned g_sense = 0;

typedef unsigned long long u64;

// ---------------- packed f32x2 helpers (Blackwell FFMA2: PTX-only) --------
__device__ __forceinline__ u64 pack2(float x) {
    u64 r; asm("mov.b64 %0, {%1, %1};" : "=l"(r) : "f"(x)); return r;
}
__device__ __forceinline__ void fma2(u64& d, u64 a, u64 b) {
    asm("fma.rn.f32x2 %0, %1, %2, %0;" : "+l"(d) : "l"(a), "l"(b));
}
// L2-only loads for cross-SM-mutated data (L1 not coherent within a
// persistent kernel -> .cg is load-bearing for correctness)
__device__ __forceinline__ float4 ldcg4(const float* p) {
    float4 v;
    asm("ld.global.cg.v4.f32 {%0,%1,%2,%3}, [%4];"
        : "=f"(v.x), "=f"(v.y), "=f"(v.z), "=f"(v.w) : "l"(p));
    return v;
}
__device__ __forceinline__ float ldcg(const float* p) {
    float v; asm("ld.global.cg.f32 %0, [%1];" : "=f"(v) : "l"(p)); return v;
}

// ---------------- grid-wide sense-reversing barrier -----------------------
// Total barriers per launch is EVEN, so g_sense/g_count return to (0,0)
// before the next graph replay (device globals persist across replays).
__device__ __forceinline__ void grid_barrier(unsigned& lsense) {
    __syncthreads();
    if (threadIdx.x == 0) {
        unsigned s = lsense ^ 1u;
        __threadfence();
        if (atomicAdd(&g_count, 1u) == GRID_ - 1u) {
            atomicExch(&g_count, 0u);
            __threadfence();
            atomicExch(&g_sense, s);
        } else {
            volatile unsigned* gs = &g_sense;
            while (*gs != s) { }
            __threadfence();
        }
        lsense = s;
    }
    __syncthreads();
}

// ---------------- main persistent kernel ----------------------------------
__global__ void __launch_bounds__(TPB_, 1)
snn_kernel(const float* __restrict__ W, const float* __restrict__ x0,
           const float* __restrict__ V0, const float* __restrict__ Y0,
           float* __restrict__ out)
{
    // Y staged in smem: 4 slices x 128 k x 16 b  (32 KB)
    __shared__ float Ys[4 * KSL * B_];
    __shared__ float tile[32][33];

    const int g = blockIdx.x;
    const int t = threadIdx.x;
    unsigned lsense = 0;

    // ---- init A: tiled transpose W -> g_Wt (coalesced both sides) ----
    {
        const int TPR = N_ / 32;            // 128 tiles per side
        const int i = t >> 5, j = t & 31;   // 8 rows x 32 cols per pass
        for (int tt = g; tt < TPR * TPR; tt += GRID_) {
            const int trow = tt / TPR;      // n-block
            const int tcol = tt % TPR;      // k-block
            #pragma unroll
            for (int r = 0; r < 32; r += 8)
                tile[r + i][j] = W[(size_t)(trow * 32 + r + i) * N_ + tcol * 32 + j];
            __syncthreads();
            #pragma unroll
            for (int r = 0; r < 32; r += 8)
                g_Wt[(size_t)(tcol * 32 + r + i) * N_ + trow * 32 + j] = tile[j][r + i];
            __syncthreads();
        }
    }

    // ---- init B: pack Y0 -> Yp[k][b] ----
    for (int m = g * TPB_ + t; m < N_ * B_; m += GRID_ * TPB_) {
        const int k = m >> 4, b = m & 15;
        g_Yp[m] = Y0[b * N_ + k];
    }

    // ---- per-thread neuron state, kept in registers for all 500 steps ----
    const int u  = g * TPB_ + t;            // 0..32767
    const int m0 = u, m1 = u + GRID_ * TPB_;
    const int k0n = m0 >> 4, b0n = m0 & 15;
    const int k1n = m1 >> 4, b1n = m1 & 15;
    float Vr0 = V0[b0n * N_ + k0n], Vr1 = V0[b1n * N_ + k1n];
    float Yr0 = Y0[b0n * N_ + k0n], Yr1 = Y0[b1n * N_ + k1n];
    const float xr0 = x0[b0n * N_ + k0n], xr1 = x0[b1n * N_ + k1n];
    float Rr0 = 0.0f, Rr1 = 0.0f;

    // ---- GEMM task mapping: (n-tile, k-slice) ----
    const int nt  = g >> 3;                      // 0..15  (256 n each)
    const int n   = nt * 256 + 4 * (t & 63);     // this thread's 4-n group
    const int h   = t >> 6;                      // 0..3: which slice in block
    const int sg  = g & 7;                       // slice group
    const int sl  = 4 * sg + h;                  // k-slice 0..31
    const float* wt_base = g_Wt + (size_t)sl * KSL * N_ + n;
    float*       zp      = g_Zpart + ((size_t)sl * N_ + n) * B_;
    const float* yg      = g_Yp + sg * 4 * KSL * B_;  // 32 KB contiguous (4 slices)
    const float* ysm     = Ys + h * (KSL * B_);

    grid_barrier(lsense);                        // barrier 1: init done

    const float cY    = (float)(0.1 / 8.0);         // dt / tausyn
    const float scale = (float)(0.1 / (500 * 0.1)); // dt / T

    for (int step = 0; step < NT_; ++step) {
        // ---- stage this block's 4 Y slices into smem (coalesced, L2 reads)
        #pragma unroll
        for (int i = 0; i < (4 * KSL * B_) / (4 * TPB_); ++i) {  // 8 float4/thread
            const int idx = (i * TPB_ + t) * 4;
            const float4 v = ldcg4(yg + idx);
            *reinterpret_cast<float4*>(&Ys[idx]) = v;
        }
        __syncthreads();

        // ======== phase 1: partial GEMM (4 n-rows x 16 batches, 128 k) ====
        u64 A0[8], A1[8], A2[8], A3[8];
        #pragma unroll
        for (int j = 0; j < 8; ++j) { A0[j] = 0ull; A1[j] = 0ull; A2[j] = 0ull; A3[j] = 0ull; }

        const float* wp = wt_base;
        #pragma unroll 8
        for (int kk = 0; kk < KSL; ++kk) {
            const float4 w4 = *reinterpret_cast<const float4*>(wp);
            const u64 w0 = pack2(w4.x);
            const u64 w1 = pack2(w4.y);
            const u64 w2 = pack2(w4.z);
            const u64 w3 = pack2(w4.w);
            // Y row from smem: same address across the warp -> LDS broadcast
            const ulonglong2* yrow =
                reinterpret_cast<const ulonglong2*>(ysm + kk * B_);
            const ulonglong2 p0 = yrow[0];
            const ulonglong2 p1 = yrow[1];
            const ulonglong2 p2 = yrow[2];
            const ulonglong2 p3 = yrow[3];
            fma2(A0[0], w0, p0.x); fma2(A1[0], w1, p0.x); fma2(A2[0], w2, p0.x); fma2(A3[0], w3, p0.x);
            fma2(A0[1], w0, p0.y); fma2(A1[1], w1, p0.y); fma2(A2[1], w2, p0.y); fma2(A3[1], w3, p0.y);
            fma2(A0[2], w0, p1.x); fma2(A1[2], w1, p1.x); fma2(A2[2], w2, p1.x); fma2(A3[2], w3, p1.x);
            fma2(A0[3], w0, p1.y); fma2(A1[3], w1, p1.y); fma2(A2[3], w2, p1.y); fma2(A3[3], w3, p1.y);
            fma2(A0[4], w0, p2.x); fma2(A1[4], w1, p2.x); fma2(A2[4], w2, p2.x); fma2(A3[4], w3, p2.x);
            fma2(A0[5], w0, p2.y); fma2(A1[5], w1, p2.y); fma2(A2[5], w2, p2.y); fma2(A3[5], w3, p2.y);
            fma2(A0[6], w0, p3.x); fma2(A1[6], w1, p3.x); fma2(A2[6], w2, p3.x); fma2(A3[6], w3, p3.x);
            fma2(A0[7], w0, p3.y); fma2(A1[7], w1, p3.y); fma2(A2[7], w2, p3.y); fma2(A3[7], w3, p3.y);
            wp += N_;
        }
        // store 64 partials (four contiguous 64B rows)
        {
            union F2 { u64 u; float2 f; };
            float4* z4 = reinterpret_cast<float4*>(zp);
            #pragma unroll
            for (int j = 0; j < 4; ++j) {
                F2 a{A0[2 * j]}, b{A0[2 * j + 1]};
                z4[j] = make_float4(a.f.x, a.f.y, b.f.x, b.f.y);
            }
            #pragma unroll
            for (int j = 0; j < 4; ++j) {
                F2 a{A1[2 * j]}, b{A1[2 * j + 1]};
                z4[4 + j] = make_float4(a.f.x, a.f.y, b.f.x, b.f.y);
            }
            #pragma unroll
            for (int j = 0; j < 4; ++j) {
                F2 a{A2[2 * j]}, b{A2[2 * j + 1]};
                z4[8 + j] = make_float4(a.f.x, a.f.y, b.f.x, b.f.y);
            }
            #pragma unroll
            for (int j = 0; j < 4; ++j) {
                F2 a{A3[2 * j]}, b{A3[2 * j + 1]};
                z4[12 + j] = make_float4(a.f.x, a.f.y, b.f.x, b.f.y);
            }
        }

        grid_barrier(lsense);                    // partials visible

        // ======== phase 2: neuron update (2 items, state in registers) ====
        {
            float Z = xr0;
            #pragma unroll
            for (int s2 = 0; s2 < NSLICE; ++s2)
                Z += ldcg(g_Zpart + ((size_t)s2 * N_ + k0n) * B_ + b0n);
            float num = -(Vr0 - (-72.0f));
            num = num + expf(Vr0 - (-55.0f));
            num = num + Z;
            const float dV = num / 10.0f;
            float Vn = Vr0 + 0.1f * dV;
            Vn = fmaxf(Vn, -85.0f);
            const bool sp = (Vn >= 0.0f);
            const float S = sp ? 10.0f : 0.0f;
            if (sp) Vn = -72.0f;
            Vr0 = Vn;
            Yr0 = Yr0 + cY * (S - Yr0);
            Rr0 += S;
            g_Yp[m0] = Yr0;
        }
        {
            float Z = xr1;
            #pragma unroll
            for (int s2 = 0; s2 < NSLICE; ++s2)
                Z += ldcg(g_Zpart + ((size_t)s2 * N_ + k1n) * B_ + b1n);
            float num = -(Vr1 - (-72.0f));
            num = num + expf(Vr1 - (-55.0f));
            num = num + Z;
            const float dV = num / 10.0f;
            float Vn = Vr1 + 0.1f * dV;
            Vn = fmaxf(Vn, -85.0f);
            const bool sp = (Vn >= 0.0f);
            const float S = sp ? 10.0f : 0.0f;
            if (sp) Vn = -72.0f;
            Vr1 = Vn;
            Yr1 = Yr1 + cY * (S - Yr1);
            Rr1 += S;
            g_Yp[m1] = Yr1;
        }

        grid_barrier(lsense);                    // Yp visible for next step
    }

    // ---- output: r * dt/T  (layout out[b][n]) ----
    out[b0n * N_ + k0n] = Rr0 * scale;
    out[b1n * N_ + k1n] = Rr1 * scale;

    grid_barrier(lsense);  // pad: total = 1 + 2*NT_ + 1 = 1002 (even)
}

extern "C" void kernel_launch(void* const* d_in, const int* in_sizes, int n_in,
                              void* d_out, int out_size)
{
    (void)in_sizes; (void)n_in; (void)out_size;
    const float* W  = (const float*)d_in[0];
    const float* x0 = (const float*)d_in[1];
    const float* V0 = (const float*)d_in[2];
    const float* Y0 = (const float*)d_in[3];
    snn_kernel<<<GRID_, TPB_>>>(W, x0, V0, Y0, (float*)d_out);
}